// round 16
// baseline (speedup 1.0000x reference)
#include <cuda_runtime.h>
#include <cuda_fp16.h>
#include <math.h>
#include <stdint.h>

#define TSEQ   4096
#define DEMB   1024
#define NHEADS 16
#define DKH    64
#define HDIM   1024

// Scratch (allocation-free rule: __device__ globals)
__device__ uint32_t g_xh[TSEQ * DEMB / 2];     // x fp16
__device__ uint32_t g_wqh[DEMB * HDIM / 2];    // weights fp16
__device__ uint32_t g_wkh[DEMB * HDIM / 2];
__device__ uint32_t g_wvh[DEMB * HDIM / 2];
__device__ uint32_t g_woh[HDIM * HDIM / 2];
__device__ uint32_t g_qh[TSEQ * HDIM / 2];     // rotary Q fp16 (pre-scaled 0.125*log2e)
__device__ uint32_t g_kh[TSEQ * HDIM / 2];     // rotary K fp16
__device__ uint32_t g_vh[TSEQ * HDIM / 2];     // V fp16
__device__ uint32_t g_ah[TSEQ * HDIM / 2];     // attn out fp16

#define ROPE_C  0.4152410118609203f    // log2(10000)/32
#define QSCALE  0.1803368801111204f    // 0.125 * log2(e)  (exp2-domain logits)

__device__ __forceinline__ uint32_t pack2(float lo, float hi) {
    __half2 h = __floats2half2_rn(lo, hi);
    return *(uint32_t*)&h;
}

// two exps in one MUFU op; returns packed fp16x2 (A-fragment ready)
__device__ __forceinline__ uint32_t h2ex2(float x, float y) {
    uint32_t p = pack2(x, y);
    asm("ex2.approx.f16x2 %0, %0;" : "+r"(p));
    return p;
}

__device__ __forceinline__ void mma_f16(float c[4], const uint32_t a[4], const uint32_t b[2]) {
    asm volatile(
        "mma.sync.aligned.m16n8k16.row.col.f32.f16.f16.f32 "
        "{%0,%1,%2,%3},{%4,%5,%6,%7},{%8,%9},{%0,%1,%2,%3};\n"
        : "+f"(c[0]), "+f"(c[1]), "+f"(c[2]), "+f"(c[3])
        : "r"(a[0]), "r"(a[1]), "r"(a[2]), "r"(a[3]), "r"(b[0]), "r"(b[1]));
}

__device__ __forceinline__ void ldsm_x4(uint32_t& r0, uint32_t& r1, uint32_t& r2, uint32_t& r3,
                                        uint32_t addr) {
    asm volatile("ldmatrix.sync.aligned.m8n8.x4.shared.b16 {%0,%1,%2,%3}, [%4];"
                 : "=r"(r0), "=r"(r1), "=r"(r2), "=r"(r3) : "r"(addr));
}

__device__ __forceinline__ void ldsm_x4_t(uint32_t& r0, uint32_t& r1, uint32_t& r2, uint32_t& r3,
                                          uint32_t addr) {
    asm volatile("ldmatrix.sync.aligned.m8n8.x4.trans.shared.b16 {%0,%1,%2,%3}, [%4];"
                 : "=r"(r0), "=r"(r1), "=r"(r2), "=r"(r3) : "r"(addr));
}

__device__ __forceinline__ void cp16(uint32_t smem, const void* gmem) {
    asm volatile("cp.async.cg.shared.global [%0], [%1], 16;\n" :: "r"(smem), "l"(gmem));
}
__device__ __forceinline__ void cp_commit() {
    asm volatile("cp.async.commit_group;\n");
}
template <int N> __device__ __forceinline__ void cp_wait() {
    asm volatile("cp.async.wait_group %0;\n" :: "n"(N));
}

// ---------------------------------------------------------------------------
// One-shot fp32 -> fp16 conversion of x + 4 weight matrices.
// ---------------------------------------------------------------------------
#define XW4 (TSEQ * DEMB / 4)
#define WW4 (DEMB * HDIM / 4)

__global__ void cvt_all_kernel(const float4* __restrict__ x,
                               const float4* __restrict__ wq, const float4* __restrict__ wk,
                               const float4* __restrict__ wv, const float4* __restrict__ wo,
                               uint2* __restrict__ xh,
                               uint2* __restrict__ wqh, uint2* __restrict__ wkh,
                               uint2* __restrict__ wvh, uint2* __restrict__ woh) {
    const int i = blockIdx.x * blockDim.x + threadIdx.x;
    const float4* src;
    uint2* dst;
    int off;
    if (i < XW4)                { src = x;  dst = xh;  off = i; }
    else {
        const int j = i - XW4;
        const int seg = j / WW4;
        off = j - seg * WW4;
        switch (seg) {
            case 0:  src = wq; dst = wqh; break;
            case 1:  src = wk; dst = wkh; break;
            case 2:  src = wv; dst = wvh; break;
            default: src = wo; dst = woh; break;
        }
    }
    float4 v = src[off];
    uint2 u;
    u.x = pack2(v.x, v.y);
    u.y = pack2(v.z, v.w);
    dst[off] = u;
}

// ---------------------------------------------------------------------------
// Fused QKV GEMM (+RoPE for Q/K): blockIdx.z selects {Q,K,V}.
// Block 128x128, 8 warps, BK=64, 3-stage cp.async ring, SW128 swizzle.
// (R11-verified mainloop.)
// ---------------------------------------------------------------------------
#define ST_S 130   // epilogue staging row stride (floats)

__global__ __launch_bounds__(256, 2) void qkv_gemm_kernel(
    const __half* __restrict__ A,
    const __half* __restrict__ Bq, const __half* __restrict__ Bk, const __half* __restrict__ Bv,
    const float* __restrict__ bq, const float* __restrict__ bk, const float* __restrict__ bv,
    uint32_t* __restrict__ Oq, uint32_t* __restrict__ Ok, uint32_t* __restrict__ Ov)
{
    extern __shared__ char smem[];
    const uint32_t sbase = (uint32_t)__cvta_generic_to_shared(smem);

    const int z = blockIdx.z;
    const __half* B    = (z == 0) ? Bq : (z == 1) ? Bk : Bv;
    const float*  bias = (z == 0) ? bq : (z == 1) ? bk : bv;
    uint32_t*     Oh   = (z == 0) ? Oq : (z == 1) ? Ok : Ov;

    const int tid  = threadIdx.x;
    const int lane = tid & 31;
    const int wid  = tid >> 5;
    const int g    = lane >> 2;
    const int t    = lane & 3;
    const int wm   = (wid >> 2) * 64;
    const int wn   = (wid & 3) * 32;
    const int gm   = blockIdx.y * 128;
    const int gn   = blockIdx.x * 128;
    const int nk   = DEMB >> 6;

    float acc[4][4][4];
#pragma unroll
    for (int i = 0; i < 4; i++)
#pragma unroll
        for (int j = 0; j < 4; j++)
#pragma unroll
            for (int e = 0; e < 4; e++) acc[i][j][e] = 0.0f;

    auto issue = [&](int kc, int st) {
        const uint32_t sa = sbase + st * 32768;
#pragma unroll
        for (int i = 0; i < 4; i++) {
            const int idx = tid + 256 * i;
            const int r = idx >> 3, c = idx & 7;
            cp16(sa + r * 128 + ((c ^ (r & 7)) << 4),
                 A + (size_t)(gm + r) * DEMB + kc * 64 + c * 8);
        }
#pragma unroll
        for (int i = 0; i < 4; i++) {
            const int idx = tid + 256 * i;
            const int r = idx >> 4, c = idx & 15;
            cp16(sa + 16384 + r * 256 + ((c ^ (r & 7)) << 4),
                 B + (size_t)(kc * 64 + r) * HDIM + gn + c * 8);
        }
        cp_commit();
    };

    issue(0, 0);
    issue(1, 1);

#pragma unroll 1
    for (int kc = 0; kc < nk; kc++) {
        if (kc < nk - 1) cp_wait<1>(); else cp_wait<0>();
        __syncthreads();
        if (kc + 2 < nk) issue(kc + 2, (kc + 2) % 3);

        const uint32_t sa = sbase + (kc % 3) * 32768;
#pragma unroll
        for (int kk = 0; kk < 64; kk += 16) {
            uint32_t af[4][4], bf[4][2];
#pragma unroll
            for (int i = 0; i < 4; i++) {
                const int row = wm + i * 16 + (lane & 15);
                const int ch  = (kk >> 3) + (lane >> 4);
                ldsm_x4(af[i][0], af[i][1], af[i][2], af[i][3],
                        sa + row * 128 + ((ch ^ (row & 7)) << 4));
            }
#pragma unroll
            for (int nb = 0; nb < 2; nb++) {
                const int row = kk + ((lane & 7) | (lane & 8));
                const int ch  = ((wn + nb * 16) >> 3) + ((lane >> 4) & 1);
                ldsm_x4_t(bf[2 * nb][0], bf[2 * nb][1], bf[2 * nb + 1][0], bf[2 * nb + 1][1],
                          sa + 16384 + row * 256 + ((ch ^ (row & 7)) << 4));
            }
#pragma unroll
            for (int i = 0; i < 4; i++)
#pragma unroll
                for (int j = 0; j < 4; j++)
                    mma_f16(acc[i][j], af[i], bf[j]);
        }
    }

    if (z == 2) {
#pragma unroll
        for (int i = 0; i < 4; i++) {
            const int row0 = gm + wm + i * 16 + g;
#pragma unroll
            for (int j = 0; j < 4; j++) {
                const int col = gn + wn + j * 8 + 2 * t;
                const float2 bv2 = *(const float2*)&bias[col];
                Oh[(row0 * HDIM + col) >> 1]       = pack2(acc[i][j][0] + bv2.x, acc[i][j][1] + bv2.y);
                Oh[((row0 + 8) * HDIM + col) >> 1] = pack2(acc[i][j][2] + bv2.x, acc[i][j][3] + bv2.y);
            }
        }
        return;
    }

    // Q/K: stage fp32 tile in smem, apply RoPE, write fp16
    __syncthreads();
    float* st = (float*)smem;  // [128][ST_S]
#pragma unroll
    for (int i = 0; i < 4; i++) {
        const int r0 = wm + i * 16 + g;
#pragma unroll
        for (int j = 0; j < 4; j++) {
            const int col = wn + j * 8 + 2 * t;
            const float2 bv2 = *(const float2*)&bias[gn + col];
            float2 v0, v1;
            v0.x = acc[i][j][0] + bv2.x;  v0.y = acc[i][j][1] + bv2.y;
            v1.x = acc[i][j][2] + bv2.x;  v1.y = acc[i][j][3] + bv2.y;
            *(float2*)&st[r0 * ST_S + col]       = v0;
            *(float2*)&st[(r0 + 8) * ST_S + col] = v1;
        }
    }
    __syncthreads();

    const float sc = (z == 0) ? QSCALE : 1.0f;
#pragma unroll 1
    for (int it = 0; it < 16; it++) {
        const int idx = it * 256 + tid;     // 0..4095
        const int row = idx >> 5;           // 0..127
        const int pp  = idx & 31;
        const int hs  = pp >> 4;
        const int pi  = pp & 15;
        const int c0  = hs * 64 + 2 * pi;
        const int pos = gm + row;

        float s0, cc0, s1, cc1;
        sincosf((float)pos * exp2f(-(float)(2 * pi)     * ROPE_C), &s0, &cc0);
        sincosf((float)pos * exp2f(-(float)(2 * pi + 1) * ROPE_C), &s1, &cc1);

        const float2 x1 = *(const float2*)&st[row * ST_S + c0];
        const float2 x2 = *(const float2*)&st[row * ST_S + c0 + 32];

        const uint32_t o1 = pack2((x1.x * cc0 - x2.x * s0) * sc, (x1.y * cc1 - x2.y * s1) * sc);
        const uint32_t o2 = pack2((x2.x * cc0 + x1.x * s0) * sc, (x2.y * cc1 + x1.y * s1) * sc);

        const int ui = pos * (HDIM / 2) + ((gn + c0) >> 1);
        Oh[ui]      = o1;
        Oh[ui + 16] = o2;
    }
}

// ---------------------------------------------------------------------------
// Out-projection GEMM: fp16 A,B -> fp32 out (+bias).  (R11-verified)
// ---------------------------------------------------------------------------
__global__ __launch_bounds__(256, 2) void gemm_f16_f32_kernel(
    const __half* __restrict__ A, const __half* __restrict__ B,
    const float* __restrict__ bias, float* __restrict__ C,
    int M, int N, int K)
{
    extern __shared__ char smem[];
    const uint32_t sbase = (uint32_t)__cvta_generic_to_shared(smem);

    const int tid  = threadIdx.x;
    const int lane = tid & 31;
    const int wid  = tid >> 5;
    const int g    = lane >> 2;
    const int t    = lane & 3;
    const int wm   = (wid >> 2) * 64;
    const int wn   = (wid & 3) * 32;
    const int gm   = blockIdx.y * 128;
    const int gn   = blockIdx.x * 128;
    const int nk   = K >> 6;

    float acc[4][4][4];
#pragma unroll
    for (int i = 0; i < 4; i++)
#pragma unroll
        for (int j = 0; j < 4; j++)
#pragma unroll
            for (int e = 0; e < 4; e++) acc[i][j][e] = 0.0f;

    auto issue = [&](int kc, int st) {
        const uint32_t sa = sbase + st * 32768;
#pragma unroll
        for (int i = 0; i < 4; i++) {
            const int idx = tid + 256 * i;
            const int r = idx >> 3, c = idx & 7;
            cp16(sa + r * 128 + ((c ^ (r & 7)) << 4),
                 A + (size_t)(gm + r) * K + kc * 64 + c * 8);
        }
#pragma unroll
        for (int i = 0; i < 4; i++) {
            const int idx = tid + 256 * i;
            const int r = idx >> 4, c = idx & 15;
            cp16(sa + 16384 + r * 256 + ((c ^ (r & 7)) << 4),
                 B + (size_t)(kc * 64 + r) * N + gn + c * 8);
        }
        cp_commit();
    };

    issue(0, 0);
    issue(1, 1);

#pragma unroll 1
    for (int kc = 0; kc < nk; kc++) {
        if (kc < nk - 1) cp_wait<1>(); else cp_wait<0>();
        __syncthreads();
        if (kc + 2 < nk) issue(kc + 2, (kc + 2) % 3);

        const uint32_t sa = sbase + (kc % 3) * 32768;
#pragma unroll
        for (int kk = 0; kk < 64; kk += 16) {
            uint32_t af[4][4], bf[4][2];
#pragma unroll
            for (int i = 0; i < 4; i++) {
                const int row = wm + i * 16 + (lane & 15);
                const int ch  = (kk >> 3) + (lane >> 4);
                ldsm_x4(af[i][0], af[i][1], af[i][2], af[i][3],
                        sa + row * 128 + ((ch ^ (row & 7)) << 4));
            }
#pragma unroll
            for (int nb = 0; nb < 2; nb++) {
                const int row = kk + ((lane & 7) | (lane & 8));
                const int ch  = ((wn + nb * 16) >> 3) + ((lane >> 4) & 1);
                ldsm_x4_t(bf[2 * nb][0], bf[2 * nb][1], bf[2 * nb + 1][0], bf[2 * nb + 1][1],
                          sa + 16384 + row * 256 + ((ch ^ (row & 7)) << 4));
            }
#pragma unroll
            for (int i = 0; i < 4; i++)
#pragma unroll
                for (int j = 0; j < 4; j++)
                    mma_f16(acc[i][j], af[i], bf[j]);
        }
    }

#pragma unroll
    for (int i = 0; i < 4; i++) {
        const int row0 = gm + wm + i * 16 + g;
#pragma unroll
        for (int j = 0; j < 4; j++) {
            const int col = gn + wn + j * 8 + 2 * t;
            const float2 bv = *(const float2*)&bias[col];
            float2 o0, o1;
            o0.x = acc[i][j][0] + bv.x;  o0.y = acc[i][j][1] + bv.y;
            o1.x = acc[i][j][2] + bv.x;  o1.y = acc[i][j][3] + bv.y;
            *(float2*)&C[row0 * N + col]       = o0;
            *(float2*)&C[(row0 + 8) * N + col] = o1;
        }
    }
}

// ---------------------------------------------------------------------------
// Flash attention fp16. Block = (256 q rows, head), 8 warps x 32 q-rows
// (each K/V ldsm feeds 4 MMAs). KV staged 128 keys/round but softmax runs in
// TWO 64-key sub-rounds so s[] is [2][8][4] (64 regs) — no spills (~190 regs).
// 2-stage ring, depth-1 prefetch; exp2 softmax (ex2.approx.f16x2); ones-MMA
// row-sums. Smem: 32KB Q + 2*32KB = 96KB. 1 CTA/SM.
// ---------------------------------------------------------------------------
__global__ __launch_bounds__(256, 1) void flash_f16_kernel(
    const __half* __restrict__ Qh, const __half* __restrict__ Kh,
    const __half* __restrict__ Vh, uint32_t* __restrict__ Oh)
{
    extern __shared__ char smem[];
    const uint32_t sbase = (uint32_t)__cvta_generic_to_shared(smem);

    const int h    = blockIdx.y;
    const int q0   = blockIdx.x * 256;
    const int tid  = threadIdx.x;
    const int lane = tid & 31;
    const int wid  = tid >> 5;
    const int g    = lane >> 2;
    const int t    = lane & 3;
    const int wm   = wid * 32;
    const int ntiles = TSEQ / 128;

    auto issue_tile = [&](int tile, int st) {
        const uint32_t kb = sbase + 32768 + st * 32768;
        const int kv0 = tile * 128;
#pragma unroll
        for (int i = 0; i < 4; i++) {
            const int idx = tid + 256 * i;
            const int r = idx >> 3, c = idx & 7;
            const uint32_t off = r * 128 + ((c ^ (r & 7)) << 4);
            const size_t go = (size_t)(kv0 + r) * HDIM + h * DKH + c * 8;
            cp16(kb + off,         Kh + go);
            cp16(kb + 16384 + off, Vh + go);
        }
        cp_commit();
    };

    // stage Q: 256 rows x 128B
#pragma unroll
    for (int i = 0; i < 8; i++) {
        const int idx = tid + 256 * i;
        const int r = idx >> 3, c = idx & 7;
        cp16(sbase + r * 128 + ((c ^ (r & 7)) << 4),
             Qh + (size_t)(q0 + r) * HDIM + h * DKH + c * 8);
    }
    issue_tile(0, 0);

    float o[2][8][4];
#pragma unroll
    for (int f = 0; f < 2; f++)
#pragma unroll
        for (int j = 0; j < 8; j++)
#pragma unroll
            for (int e = 0; e < 4; e++) o[f][j][e] = 0.0f;
    float ls0[4] = {0.0f, 0.0f, 0.0f, 0.0f};
    float ls1[4] = {0.0f, 0.0f, 0.0f, 0.0f};
    float m[4] = {-INFINITY, -INFINITY, -INFINITY, -INFINITY};
    const uint32_t bones[2] = {0x3C003C00u, 0x3C003C00u};

#pragma unroll 1
    for (int ti = 0; ti < ntiles; ti++) {
        cp_wait<0>();
        __syncthreads();
        if (ti + 1 < ntiles) issue_tile(ti + 1, (ti + 1) & 1);

        const uint32_t kb = sbase + 32768 + (ti & 1) * 32768;
        const uint32_t vb = kb + 16384;

#pragma unroll
        for (int half = 0; half < 2; half++) {
            const int ko = half << 6;    // 0 or 64 (key offset in staged tile)

            // S = Q @ K^T: per warp 32 q-rows x 64 keys (exp2-domain logits)
            float s[2][8][4];
#pragma unroll
            for (int f = 0; f < 2; f++)
#pragma unroll
                for (int j = 0; j < 8; j++)
#pragma unroll
                    for (int e = 0; e < 4; e++) s[f][j][e] = 0.0f;

#pragma unroll
            for (int kk = 0; kk < 64; kk += 16) {
                uint32_t a0[4], a1[4];
                {
                    const int row = wm + (lane & 15);
                    const int ch  = (kk >> 3) + (lane >> 4);
                    ldsm_x4(a0[0], a0[1], a0[2], a0[3],
                            sbase + row * 128 + ((ch ^ (row & 7)) << 4));
                    const int row1 = row + 16;
                    ldsm_x4(a1[0], a1[1], a1[2], a1[3],
                            sbase + row1 * 128 + ((ch ^ (row1 & 7)) << 4));
                }
#pragma unroll
                for (int j0 = 0; j0 < 8; j0 += 2) {
                    uint32_t r0, r1, r2, r3;
                    const int row = ko + j0 * 8 + (lane & 15);
                    const int ch  = (kk >> 3) + (lane >> 4);
                    ldsm_x4(r0, r1, r2, r3, kb + row * 128 + ((ch ^ (row & 7)) << 4));
                    uint32_t b0[2] = {r0, r2};
                    uint32_t b1[2] = {r1, r3};
                    mma_f16(s[0][j0],     a0, b0);
                    mma_f16(s[0][j0 + 1], a0, b1);
                    mma_f16(s[1][j0],     a1, b0);
                    mma_f16(s[1][j0 + 1], a1, b1);
                }
            }

            // online softmax: 4 row-groups (wm+g, +8, +16, +24) over 64 cols
            float mx[4] = {-INFINITY, -INFINITY, -INFINITY, -INFINITY};
#pragma unroll
            for (int j = 0; j < 8; j++) {
                mx[0] = fmaxf(mx[0], fmaxf(s[0][j][0], s[0][j][1]));
                mx[1] = fmaxf(mx[1], fmaxf(s[0][j][2], s[0][j][3]));
                mx[2] = fmaxf(mx[2], fmaxf(s[1][j][0], s[1][j][1]));
                mx[3] = fmaxf(mx[3], fmaxf(s[1][j][2], s[1][j][3]));
            }
#pragma unroll
            for (int r = 0; r < 4; r++) {
                mx[r] = fmaxf(mx[r], __shfl_xor_sync(0xffffffffu, mx[r], 1));
                mx[r] = fmaxf(mx[r], __shfl_xor_sync(0xffffffffu, mx[r], 2));
            }

            float mn[4], fr[4];
#pragma unroll
            for (int r = 0; r < 4; r++) {
                mn[r] = fmaxf(m[r], mx[r]);
                fr[r] = exp2f(m[r] - mn[r]);
                m[r]  = mn[r];
            }

            // rescale O and row-sum accumulators
#pragma unroll
            for (int j = 0; j < 8; j++) {
                o[0][j][0] *= fr[0]; o[0][j][1] *= fr[0];
                o[0][j][2] *= fr[1]; o[0][j][3] *= fr[1];
                o[1][j][0] *= fr[2]; o[1][j][1] *= fr[2];
                o[1][j][2] *= fr[3]; o[1][j][3] *= fr[3];
            }
            ls0[0] *= fr[0]; ls0[1] *= fr[0]; ls0[2] *= fr[1]; ls0[3] *= fr[1];
            ls1[0] *= fr[2]; ls1[1] *= fr[2]; ls1[2] *= fr[3]; ls1[3] *= fr[3];

            // O += P @ V ; ls += P @ ones
#pragma unroll
            for (int kv = 0; kv < 64; kv += 16) {
                const int j0 = kv >> 3;
                uint32_t a0[4], a1[4];
                a0[0] = h2ex2(s[0][j0][0] - mn[0],     s[0][j0][1] - mn[0]);
                a0[1] = h2ex2(s[0][j0][2] - mn[1],     s[0][j0][3] - mn[1]);
                a0[2] = h2ex2(s[0][j0 + 1][0] - mn[0], s[0][j0 + 1][1] - mn[0]);
                a0[3] = h2ex2(s[0][j0 + 1][2] - mn[1], s[0][j0 + 1][3] - mn[1]);
                a1[0] = h2ex2(s[1][j0][0] - mn[2],     s[1][j0][1] - mn[2]);
                a1[1] = h2ex2(s[1][j0][2] - mn[3],     s[1][j0][3] - mn[3]);
                a1[2] = h2ex2(s[1][j0 + 1][0] - mn[2], s[1][j0 + 1][1] - mn[2]);
                a1[3] = h2ex2(s[1][j0 + 1][2] - mn[3], s[1][j0 + 1][3] - mn[3]);
                mma_f16(ls0, a0, bones);
                mma_f16(ls1, a1, bones);
#pragma unroll
                for (int jd = 0; jd < 8; jd += 2) {
                    uint32_t b0[2], b1[2];
                    const int row = ko + kv + ((lane & 7) | (lane & 8));
                    const int ch  = jd + (lane >> 4);
                    ldsm_x4_t(b0[0], b0[1], b1[0], b1[1],
                              vb + row * 128 + ((ch ^ (row & 7)) << 4));
                    mma_f16(o[0][jd],     a0, b0);
                    mma_f16(o[0][jd + 1], a0, b1);
                    mma_f16(o[1][jd],     a1, b0);
                    mma_f16(o[1][jd + 1], a1, b1);
                }
            }
        }
    }

    const float inv0 = 1.0f / ls0[0];
    const float inv1 = 1.0f / ls0[2];
    const float inv2 = 1.0f / ls1[0];
    const float inv3 = 1.0f / ls1[2];
    const int row0 = q0 + wm + g;
#pragma unroll
    for (int jd = 0; jd < 8; jd++) {
        const int col = h * DKH + jd * 8 + 2 * t;
        Oh[row0 * (HDIM / 2) + (col >> 1)]        = pack2(o[0][jd][0] * inv0, o[0][jd][1] * inv0);
        Oh[(row0 + 8) * (HDIM / 2) + (col >> 1)]  = pack2(o[0][jd][2] * inv1, o[0][jd][3] * inv1);
        Oh[(row0 + 16) * (HDIM / 2) + (col >> 1)] = pack2(o[1][jd][0] * inv2, o[1][jd][1] * inv2);
        Oh[(row0 + 24) * (HDIM / 2) + (col >> 1)] = pack2(o[1][jd][2] * inv3, o[1][jd][3] * inv3);
    }
}

// ---------------------------------------------------------------------------
extern "C" void kernel_launch(void* const* d_in, const int* in_sizes, int n_in,
                              void* d_out, int out_size) {
    const float* x  = (const float*)d_in[0];
    const float* Wq = (const float*)d_in[1];
    const float* bq = (const float*)d_in[2];
    const float* Wk = (const float*)d_in[3];
    const float* bk = (const float*)d_in[4];
    const float* Wv = (const float*)d_in[5];
    const float* bv = (const float*)d_in[6];
    const float* Wo = (const float*)d_in[7];
    const float* bo = (const float*)d_in[8];
    float* out = (float*)d_out;

    uint32_t *xh, *wqh, *wkh, *wvh, *woh, *qh, *kh, *vh, *ah;
    cudaGetSymbolAddress((void**)&xh,  g_xh);
    cudaGetSymbolAddress((void**)&wqh, g_wqh);
    cudaGetSymbolAddress((void**)&wkh, g_wkh);
    cudaGetSymbolAddress((void**)&wvh, g_wvh);
    cudaGetSymbolAddress((void**)&woh, g_woh);
    cudaGetSymbolAddress((void**)&qh,  g_qh);
    cudaGetSymbolAddress((void**)&kh,  g_kh);
    cudaGetSymbolAddress((void**)&vh,  g_vh);
    cudaGetSymbolAddress((void**)&ah,  g_ah);

    const int total4 = XW4 + 4 * WW4;
    cvt_all_kernel<<<(total4 + 255) / 256, 256>>>(
        (const float4*)x, (const float4*)Wq, (const float4*)Wk,
        (const float4*)Wv, (const float4*)Wo,
        (uint2*)xh, (uint2*)wqh, (uint2*)wkh, (uint2*)wvh, (uint2*)woh);

    const int gemm_smem  = 3 * 32768;           // 96 KB
    const int flash_smem = 32768 + 2 * 32768;   // 96 KB
    cudaFuncSetAttribute(qkv_gemm_kernel,
                         cudaFuncAttributeMaxDynamicSharedMemorySize, gemm_smem);
    cudaFuncSetAttribute(gemm_f16_f32_kernel,
                         cudaFuncAttributeMaxDynamicSharedMemorySize, gemm_smem);
    cudaFuncSetAttribute(flash_f16_kernel,
                         cudaFuncAttributeMaxDynamicSharedMemorySize, flash_smem);

    qkv_gemm_kernel<<<dim3(HDIM / 128, TSEQ / 128, 3), 256, gemm_smem>>>(
        (const __half*)xh,
        (const __half*)wqh, (const __half*)wkh, (const __half*)wvh,
        bq, bk, bv, qh, kh, vh);

    flash_f16_kernel<<<dim3(TSEQ / 256, NHEADS), 256, flash_smem>>>(
        (const __half*)qh, (const __half*)kh, (const __half*)vh, ah);

    gemm_f16_f32_kernel<<<dim3(HDIM / 128, TSEQ / 128), 256, gemm_smem>>>(
        (const __half*)ah, (const __half*)woh, bo, out, TSEQ, HDIM, HDIM);
}

// round 17
// speedup vs baseline: 1.0468x; 1.0468x over previous
#include <cuda_runtime.h>
#include <cuda_fp16.h>
#include <math.h>
#include <stdint.h>

#define TSEQ   4096
#define DEMB   1024
#define NHEADS 16
#define DKH    64
#define HDIM   1024

// Scratch (allocation-free rule: __device__ globals)
__device__ uint32_t g_xh[TSEQ * DEMB / 2];     // x fp16
__device__ uint32_t g_wqh[DEMB * HDIM / 2];    // weights fp16
__device__ uint32_t g_wkh[DEMB * HDIM / 2];
__device__ uint32_t g_wvh[DEMB * HDIM / 2];
__device__ uint32_t g_woh[HDIM * HDIM / 2];
__device__ uint32_t g_qh[TSEQ * HDIM / 2];     // rotary Q fp16 (pre-scaled 0.125*log2e)
__device__ uint32_t g_kh[TSEQ * HDIM / 2];     // rotary K fp16
__device__ uint32_t g_vh[TSEQ * HDIM / 2];     // V fp16
__device__ uint32_t g_ah[TSEQ * HDIM / 2];     // attn out fp16

#define ROPE_C  0.4152410118609203f    // log2(10000)/32
#define QSCALE  0.1803368801111204f    // 0.125 * log2(e)  (exp2-domain logits)

__device__ __forceinline__ uint32_t pack2(float lo, float hi) {
    __half2 h = __floats2half2_rn(lo, hi);
    return *(uint32_t*)&h;
}

// two exps in one MUFU op; returns packed fp16x2 (A-fragment ready)
__device__ __forceinline__ uint32_t h2ex2(float x, float y) {
    uint32_t p = pack2(x, y);
    asm("ex2.approx.f16x2 %0, %0;" : "+r"(p));
    return p;
}

__device__ __forceinline__ void mma_f16(float c[4], const uint32_t a[4], const uint32_t b[2]) {
    asm volatile(
        "mma.sync.aligned.m16n8k16.row.col.f32.f16.f16.f32 "
        "{%0,%1,%2,%3},{%4,%5,%6,%7},{%8,%9},{%0,%1,%2,%3};\n"
        : "+f"(c[0]), "+f"(c[1]), "+f"(c[2]), "+f"(c[3])
        : "r"(a[0]), "r"(a[1]), "r"(a[2]), "r"(a[3]), "r"(b[0]), "r"(b[1]));
}

__device__ __forceinline__ void ldsm_x4(uint32_t& r0, uint32_t& r1, uint32_t& r2, uint32_t& r3,
                                        uint32_t addr) {
    asm volatile("ldmatrix.sync.aligned.m8n8.x4.shared.b16 {%0,%1,%2,%3}, [%4];"
                 : "=r"(r0), "=r"(r1), "=r"(r2), "=r"(r3) : "r"(addr));
}

__device__ __forceinline__ void ldsm_x4_t(uint32_t& r0, uint32_t& r1, uint32_t& r2, uint32_t& r3,
                                          uint32_t addr) {
    asm volatile("ldmatrix.sync.aligned.m8n8.x4.trans.shared.b16 {%0,%1,%2,%3}, [%4];"
                 : "=r"(r0), "=r"(r1), "=r"(r2), "=r"(r3) : "r"(addr));
}

__device__ __forceinline__ void cp16(uint32_t smem, const void* gmem) {
    asm volatile("cp.async.cg.shared.global [%0], [%1], 16;\n" :: "r"(smem), "l"(gmem));
}
__device__ __forceinline__ void cp_commit() {
    asm volatile("cp.async.commit_group;\n");
}
template <int N> __device__ __forceinline__ void cp_wait() {
    asm volatile("cp.async.wait_group %0;\n" :: "n"(N));
}

// ---------------------------------------------------------------------------
// One-shot fp32 -> fp16 conversion of x + 4 weight matrices.
// ---------------------------------------------------------------------------
#define XW4 (TSEQ * DEMB / 4)
#define WW4 (DEMB * HDIM / 4)

__global__ void cvt_all_kernel(const float4* __restrict__ x,
                               const float4* __restrict__ wq, const float4* __restrict__ wk,
                               const float4* __restrict__ wv, const float4* __restrict__ wo,
                               uint2* __restrict__ xh,
                               uint2* __restrict__ wqh, uint2* __restrict__ wkh,
                               uint2* __restrict__ wvh, uint2* __restrict__ woh) {
    const int i = blockIdx.x * blockDim.x + threadIdx.x;
    const float4* src;
    uint2* dst;
    int off;
    if (i < XW4)                { src = x;  dst = xh;  off = i; }
    else {
        const int j = i - XW4;
        const int seg = j / WW4;
        off = j - seg * WW4;
        switch (seg) {
            case 0:  src = wq; dst = wqh; break;
            case 1:  src = wk; dst = wkh; break;
            case 2:  src = wv; dst = wvh; break;
            default: src = wo; dst = woh; break;
        }
    }
    float4 v = src[off];
    uint2 u;
    u.x = pack2(v.x, v.y);
    u.y = pack2(v.z, v.w);
    dst[off] = u;
}

// ---------------------------------------------------------------------------
// Fused QKV GEMM (+RoPE for Q/K): blockIdx.z selects {Q,K,V}.
// Block 128x128, 8 warps, BK=64, 3-stage cp.async ring, SW128 swizzle.
// (R11-verified mainloop.)
// ---------------------------------------------------------------------------
#define ST_S 130   // epilogue staging row stride (floats)

__global__ __launch_bounds__(256, 2) void qkv_gemm_kernel(
    const __half* __restrict__ A,
    const __half* __restrict__ Bq, const __half* __restrict__ Bk, const __half* __restrict__ Bv,
    const float* __restrict__ bq, const float* __restrict__ bk, const float* __restrict__ bv,
    uint32_t* __restrict__ Oq, uint32_t* __restrict__ Ok, uint32_t* __restrict__ Ov)
{
    extern __shared__ char smem[];
    const uint32_t sbase = (uint32_t)__cvta_generic_to_shared(smem);

    const int z = blockIdx.z;
    const __half* B    = (z == 0) ? Bq : (z == 1) ? Bk : Bv;
    const float*  bias = (z == 0) ? bq : (z == 1) ? bk : bv;
    uint32_t*     Oh   = (z == 0) ? Oq : (z == 1) ? Ok : Ov;

    const int tid  = threadIdx.x;
    const int lane = tid & 31;
    const int wid  = tid >> 5;
    const int g    = lane >> 2;
    const int t    = lane & 3;
    const int wm   = (wid >> 2) * 64;
    const int wn   = (wid & 3) * 32;
    const int gm   = blockIdx.y * 128;
    const int gn   = blockIdx.x * 128;
    const int nk   = DEMB >> 6;

    float acc[4][4][4];
#pragma unroll
    for (int i = 0; i < 4; i++)
#pragma unroll
        for (int j = 0; j < 4; j++)
#pragma unroll
            for (int e = 0; e < 4; e++) acc[i][j][e] = 0.0f;

    auto issue = [&](int kc, int st) {
        const uint32_t sa = sbase + st * 32768;
#pragma unroll
        for (int i = 0; i < 4; i++) {
            const int idx = tid + 256 * i;
            const int r = idx >> 3, c = idx & 7;
            cp16(sa + r * 128 + ((c ^ (r & 7)) << 4),
                 A + (size_t)(gm + r) * DEMB + kc * 64 + c * 8);
        }
#pragma unroll
        for (int i = 0; i < 4; i++) {
            const int idx = tid + 256 * i;
            const int r = idx >> 4, c = idx & 15;
            cp16(sa + 16384 + r * 256 + ((c ^ (r & 7)) << 4),
                 B + (size_t)(kc * 64 + r) * HDIM + gn + c * 8);
        }
        cp_commit();
    };

    issue(0, 0);
    issue(1, 1);

#pragma unroll 1
    for (int kc = 0; kc < nk; kc++) {
        if (kc < nk - 1) cp_wait<1>(); else cp_wait<0>();
        __syncthreads();
        if (kc + 2 < nk) issue(kc + 2, (kc + 2) % 3);

        const uint32_t sa = sbase + (kc % 3) * 32768;
#pragma unroll
        for (int kk = 0; kk < 64; kk += 16) {
            uint32_t af[4][4], bf[4][2];
#pragma unroll
            for (int i = 0; i < 4; i++) {
                const int row = wm + i * 16 + (lane & 15);
                const int ch  = (kk >> 3) + (lane >> 4);
                ldsm_x4(af[i][0], af[i][1], af[i][2], af[i][3],
                        sa + row * 128 + ((ch ^ (row & 7)) << 4));
            }
#pragma unroll
            for (int nb = 0; nb < 2; nb++) {
                const int row = kk + ((lane & 7) | (lane & 8));
                const int ch  = ((wn + nb * 16) >> 3) + ((lane >> 4) & 1);
                ldsm_x4_t(bf[2 * nb][0], bf[2 * nb][1], bf[2 * nb + 1][0], bf[2 * nb + 1][1],
                          sa + 16384 + row * 256 + ((ch ^ (row & 7)) << 4));
            }
#pragma unroll
            for (int i = 0; i < 4; i++)
#pragma unroll
                for (int j = 0; j < 4; j++)
                    mma_f16(acc[i][j], af[i], bf[j]);
        }
    }

    if (z == 2) {
#pragma unroll
        for (int i = 0; i < 4; i++) {
            const int row0 = gm + wm + i * 16 + g;
#pragma unroll
            for (int j = 0; j < 4; j++) {
                const int col = gn + wn + j * 8 + 2 * t;
                const float2 bv2 = *(const float2*)&bias[col];
                Oh[(row0 * HDIM + col) >> 1]       = pack2(acc[i][j][0] + bv2.x, acc[i][j][1] + bv2.y);
                Oh[((row0 + 8) * HDIM + col) >> 1] = pack2(acc[i][j][2] + bv2.x, acc[i][j][3] + bv2.y);
            }
        }
        return;
    }

    // Q/K: stage fp32 tile in smem, apply RoPE, write fp16
    __syncthreads();
    float* st = (float*)smem;  // [128][ST_S]
#pragma unroll
    for (int i = 0; i < 4; i++) {
        const int r0 = wm + i * 16 + g;
#pragma unroll
        for (int j = 0; j < 4; j++) {
            const int col = wn + j * 8 + 2 * t;
            const float2 bv2 = *(const float2*)&bias[gn + col];
            float2 v0, v1;
            v0.x = acc[i][j][0] + bv2.x;  v0.y = acc[i][j][1] + bv2.y;
            v1.x = acc[i][j][2] + bv2.x;  v1.y = acc[i][j][3] + bv2.y;
            *(float2*)&st[r0 * ST_S + col]       = v0;
            *(float2*)&st[(r0 + 8) * ST_S + col] = v1;
        }
    }
    __syncthreads();

    const float sc = (z == 0) ? QSCALE : 1.0f;
#pragma unroll 1
    for (int it = 0; it < 16; it++) {
        const int idx = it * 256 + tid;     // 0..4095
        const int row = idx >> 5;           // 0..127
        const int pp  = idx & 31;
        const int hs  = pp >> 4;
        const int pi  = pp & 15;
        const int c0  = hs * 64 + 2 * pi;
        const int pos = gm + row;

        float s0, cc0, s1, cc1;
        sincosf((float)pos * exp2f(-(float)(2 * pi)     * ROPE_C), &s0, &cc0);
        sincosf((float)pos * exp2f(-(float)(2 * pi + 1) * ROPE_C), &s1, &cc1);

        const float2 x1 = *(const float2*)&st[row * ST_S + c0];
        const float2 x2 = *(const float2*)&st[row * ST_S + c0 + 32];

        const uint32_t o1 = pack2((x1.x * cc0 - x2.x * s0) * sc, (x1.y * cc1 - x2.y * s1) * sc);
        const uint32_t o2 = pack2((x2.x * cc0 + x1.x * s0) * sc, (x2.y * cc1 + x1.y * s1) * sc);

        const int ui = pos * (HDIM / 2) + ((gn + c0) >> 1);
        Oh[ui]      = o1;
        Oh[ui + 16] = o2;
    }
}

// ---------------------------------------------------------------------------
// Out-projection GEMM: fp16 A,B -> fp32 out (+bias).  (R11-verified)
// ---------------------------------------------------------------------------
__global__ __launch_bounds__(256, 2) void gemm_f16_f32_kernel(
    const __half* __restrict__ A, const __half* __restrict__ B,
    const float* __restrict__ bias, float* __restrict__ C,
    int M, int N, int K)
{
    extern __shared__ char smem[];
    const uint32_t sbase = (uint32_t)__cvta_generic_to_shared(smem);

    const int tid  = threadIdx.x;
    const int lane = tid & 31;
    const int wid  = tid >> 5;
    const int g    = lane >> 2;
    const int t    = lane & 3;
    const int wm   = (wid >> 2) * 64;
    const int wn   = (wid & 3) * 32;
    const int gm   = blockIdx.y * 128;
    const int gn   = blockIdx.x * 128;
    const int nk   = K >> 6;

    float acc[4][4][4];
#pragma unroll
    for (int i = 0; i < 4; i++)
#pragma unroll
        for (int j = 0; j < 4; j++)
#pragma unroll
            for (int e = 0; e < 4; e++) acc[i][j][e] = 0.0f;

    auto issue = [&](int kc, int st) {
        const uint32_t sa = sbase + st * 32768;
#pragma unroll
        for (int i = 0; i < 4; i++) {
            const int idx = tid + 256 * i;
            const int r = idx >> 3, c = idx & 7;
            cp16(sa + r * 128 + ((c ^ (r & 7)) << 4),
                 A + (size_t)(gm + r) * K + kc * 64 + c * 8);
        }
#pragma unroll
        for (int i = 0; i < 4; i++) {
            const int idx = tid + 256 * i;
            const int r = idx >> 4, c = idx & 15;
            cp16(sa + 16384 + r * 256 + ((c ^ (r & 7)) << 4),
                 B + (size_t)(kc * 64 + r) * N + gn + c * 8);
        }
        cp_commit();
    };

    issue(0, 0);
    issue(1, 1);

#pragma unroll 1
    for (int kc = 0; kc < nk; kc++) {
        if (kc < nk - 1) cp_wait<1>(); else cp_wait<0>();
        __syncthreads();
        if (kc + 2 < nk) issue(kc + 2, (kc + 2) % 3);

        const uint32_t sa = sbase + (kc % 3) * 32768;
#pragma unroll
        for (int kk = 0; kk < 64; kk += 16) {
            uint32_t af[4][4], bf[4][2];
#pragma unroll
            for (int i = 0; i < 4; i++) {
                const int row = wm + i * 16 + (lane & 15);
                const int ch  = (kk >> 3) + (lane >> 4);
                ldsm_x4(af[i][0], af[i][1], af[i][2], af[i][3],
                        sa + row * 128 + ((ch ^ (row & 7)) << 4));
            }
#pragma unroll
            for (int nb = 0; nb < 2; nb++) {
                const int row = kk + ((lane & 7) | (lane & 8));
                const int ch  = ((wn + nb * 16) >> 3) + ((lane >> 4) & 1);
                ldsm_x4_t(bf[2 * nb][0], bf[2 * nb][1], bf[2 * nb + 1][0], bf[2 * nb + 1][1],
                          sa + 16384 + row * 256 + ((ch ^ (row & 7)) << 4));
            }
#pragma unroll
            for (int i = 0; i < 4; i++)
#pragma unroll
                for (int j = 0; j < 4; j++)
                    mma_f16(acc[i][j], af[i], bf[j]);
        }
    }

#pragma unroll
    for (int i = 0; i < 4; i++) {
        const int row0 = gm + wm + i * 16 + g;
#pragma unroll
        for (int j = 0; j < 4; j++) {
            const int col = gn + wn + j * 8 + 2 * t;
            const float2 bv = *(const float2*)&bias[col];
            float2 o0, o1;
            o0.x = acc[i][j][0] + bv.x;  o0.y = acc[i][j][1] + bv.y;
            o1.x = acc[i][j][2] + bv.x;  o1.y = acc[i][j][3] + bv.y;
            *(float2*)&C[row0 * N + col]       = o0;
            *(float2*)&C[(row0 + 8) * N + col] = o1;
        }
    }
}

// ---------------------------------------------------------------------------
// Flash attention fp16. Block = (128 q rows, head), 4 warps x 32 q-rows,
// 128 threads, 2 CTAs/SM (phase mixing) + 4-MMAs-per-K/V-ldsm reuse.
// KV tile 128 keys, ONE softmax round per tile (s[2][16][4]); 2-stage ring,
// depth-1 prefetch; exp2 softmax (ex2.approx.f16x2); ones-MMA row-sums.
// Smem: 16KB Q + 2*32KB = 80KB -> occ 2.
// ---------------------------------------------------------------------------
__global__ __launch_bounds__(128, 2) void flash_f16_kernel(
    const __half* __restrict__ Qh, const __half* __restrict__ Kh,
    const __half* __restrict__ Vh, uint32_t* __restrict__ Oh)
{
    extern __shared__ char smem[];
    const uint32_t sbase = (uint32_t)__cvta_generic_to_shared(smem);

    const int h    = blockIdx.y;
    const int q0   = blockIdx.x * 128;
    const int tid  = threadIdx.x;
    const int lane = tid & 31;
    const int wid  = tid >> 5;          // 0..3
    const int g    = lane >> 2;
    const int t    = lane & 3;
    const int wm   = wid * 32;
    const int ntiles = TSEQ / 128;

    auto issue_tile = [&](int tile, int st) {
        const uint32_t kb = sbase + 16384 + st * 32768;
        const int kv0 = tile * 128;
#pragma unroll
        for (int i = 0; i < 8; i++) {
            const int idx = tid + 128 * i;        // 0..1023
            const int r = idx >> 3, c = idx & 7;
            const uint32_t off = r * 128 + ((c ^ (r & 7)) << 4);
            const size_t go = (size_t)(kv0 + r) * HDIM + h * DKH + c * 8;
            cp16(kb + off,         Kh + go);
            cp16(kb + 16384 + off, Vh + go);
        }
        cp_commit();
    };

    // stage Q: 128 rows x 128B
#pragma unroll
    for (int i = 0; i < 8; i++) {
        const int idx = tid + 128 * i;
        const int r = idx >> 3, c = idx & 7;
        cp16(sbase + r * 128 + ((c ^ (r & 7)) << 4),
             Qh + (size_t)(q0 + r) * HDIM + h * DKH + c * 8);
    }
    issue_tile(0, 0);

    float o[2][8][4];
#pragma unroll
    for (int f = 0; f < 2; f++)
#pragma unroll
        for (int j = 0; j < 8; j++)
#pragma unroll
            for (int e = 0; e < 4; e++) o[f][j][e] = 0.0f;
    float ls0[4] = {0.0f, 0.0f, 0.0f, 0.0f};
    float ls1[4] = {0.0f, 0.0f, 0.0f, 0.0f};
    float m[4] = {-INFINITY, -INFINITY, -INFINITY, -INFINITY};
    const uint32_t bones[2] = {0x3C003C00u, 0x3C003C00u};

#pragma unroll 1
    for (int ti = 0; ti < ntiles; ti++) {
        cp_wait<0>();
        __syncthreads();
        if (ti + 1 < ntiles) issue_tile(ti + 1, (ti + 1) & 1);

        const uint32_t kb = sbase + 16384 + (ti & 1) * 32768;
        const uint32_t vb = kb + 16384;

        // S = Q @ K^T: per warp 32 q-rows x 128 keys (exp2-domain logits)
        float s[2][16][4];
#pragma unroll
        for (int f = 0; f < 2; f++)
#pragma unroll
            for (int j = 0; j < 16; j++)
#pragma unroll
                for (int e = 0; e < 4; e++) s[f][j][e] = 0.0f;

#pragma unroll
        for (int kk = 0; kk < 64; kk += 16) {
            uint32_t a0[4], a1[4];
            {
                const int row = wm + (lane & 15);
                const int ch  = (kk >> 3) + (lane >> 4);
                ldsm_x4(a0[0], a0[1], a0[2], a0[3],
                        sbase + row * 128 + ((ch ^ (row & 7)) << 4));
                const int row1 = row + 16;
                ldsm_x4(a1[0], a1[1], a1[2], a1[3],
                        sbase + row1 * 128 + ((ch ^ (row1 & 7)) << 4));
            }
#pragma unroll
            for (int j0 = 0; j0 < 16; j0 += 2) {
                uint32_t r0, r1, r2, r3;
                const int row = j0 * 8 + (lane & 15);
                const int ch  = (kk >> 3) + (lane >> 4);
                ldsm_x4(r0, r1, r2, r3, kb + row * 128 + ((ch ^ (row & 7)) << 4));
                uint32_t b0[2] = {r0, r2};
                uint32_t b1[2] = {r1, r3};
                mma_f16(s[0][j0],     a0, b0);
                mma_f16(s[0][j0 + 1], a0, b1);
                mma_f16(s[1][j0],     a1, b0);
                mma_f16(s[1][j0 + 1], a1, b1);
            }
        }

        // online softmax: 4 row-groups (wm+g, +8, +16, +24) over 128 cols
        float mx[4] = {-INFINITY, -INFINITY, -INFINITY, -INFINITY};
#pragma unroll
        for (int j = 0; j < 16; j++) {
            mx[0] = fmaxf(mx[0], fmaxf(s[0][j][0], s[0][j][1]));
            mx[1] = fmaxf(mx[1], fmaxf(s[0][j][2], s[0][j][3]));
            mx[2] = fmaxf(mx[2], fmaxf(s[1][j][0], s[1][j][1]));
            mx[3] = fmaxf(mx[3], fmaxf(s[1][j][2], s[1][j][3]));
        }
#pragma unroll
        for (int r = 0; r < 4; r++) {
            mx[r] = fmaxf(mx[r], __shfl_xor_sync(0xffffffffu, mx[r], 1));
            mx[r] = fmaxf(mx[r], __shfl_xor_sync(0xffffffffu, mx[r], 2));
        }

        float mn[4], fr[4];
#pragma unroll
        for (int r = 0; r < 4; r++) {
            mn[r] = fmaxf(m[r], mx[r]);
            fr[r] = exp2f(m[r] - mn[r]);
            m[r]  = mn[r];
        }

        // rescale O and row-sum accumulators
#pragma unroll
        for (int j = 0; j < 8; j++) {
            o[0][j][0] *= fr[0]; o[0][j][1] *= fr[0];
            o[0][j][2] *= fr[1]; o[0][j][3] *= fr[1];
            o[1][j][0] *= fr[2]; o[1][j][1] *= fr[2];
            o[1][j][2] *= fr[3]; o[1][j][3] *= fr[3];
        }
        ls0[0] *= fr[0]; ls0[1] *= fr[0]; ls0[2] *= fr[1]; ls0[3] *= fr[1];
        ls1[0] *= fr[2]; ls1[1] *= fr[2]; ls1[2] *= fr[3]; ls1[3] *= fr[3];

        // O += P @ V ; ls += P @ ones
#pragma unroll
        for (int kv = 0; kv < 128; kv += 16) {
            const int j0 = kv >> 3;
            uint32_t a0[4], a1[4];
            a0[0] = h2ex2(s[0][j0][0] - mn[0],     s[0][j0][1] - mn[0]);
            a0[1] = h2ex2(s[0][j0][2] - mn[1],     s[0][j0][3] - mn[1]);
            a0[2] = h2ex2(s[0][j0 + 1][0] - mn[0], s[0][j0 + 1][1] - mn[0]);
            a0[3] = h2ex2(s[0][j0 + 1][2] - mn[1], s[0][j0 + 1][3] - mn[1]);
            a1[0] = h2ex2(s[1][j0][0] - mn[2],     s[1][j0][1] - mn[2]);
            a1[1] = h2ex2(s[1][j0][2] - mn[3],     s[1][j0][3] - mn[3]);
            a1[2] = h2ex2(s[1][j0 + 1][0] - mn[2], s[1][j0 + 1][1] - mn[2]);
            a1[3] = h2ex2(s[1][j0 + 1][2] - mn[3], s[1][j0 + 1][3] - mn[3]);
            mma_f16(ls0, a0, bones);
            mma_f16(ls1, a1, bones);
#pragma unroll
            for (int jd = 0; jd < 8; jd += 2) {
                uint32_t b0[2], b1[2];
                const int row = kv + ((lane & 7) | (lane & 8));
                const int ch  = jd + (lane >> 4);
                ldsm_x4_t(b0[0], b0[1], b1[0], b1[1],
                          vb + row * 128 + ((ch ^ (row & 7)) << 4));
                mma_f16(o[0][jd],     a0, b0);
                mma_f16(o[0][jd + 1], a0, b1);
                mma_f16(o[1][jd],     a1, b0);
                mma_f16(o[1][jd + 1], a1, b1);
            }
        }
    }

    const float inv0 = 1.0f / ls0[0];
    const float inv1 = 1.0f / ls0[2];
    const float inv2 = 1.0f / ls1[0];
    const float inv3 = 1.0f / ls1[2];
    const int row0 = q0 + wm + g;
#pragma unroll
    for (int jd = 0; jd < 8; jd++) {
        const int col = h * DKH + jd * 8 + 2 * t;
        Oh[row0 * (HDIM / 2) + (col >> 1)]        = pack2(o[0][jd][0] * inv0, o[0][jd][1] * inv0);
        Oh[(row0 + 8) * (HDIM / 2) + (col >> 1)]  = pack2(o[0][jd][2] * inv1, o[0][jd][3] * inv1);
        Oh[(row0 + 16) * (HDIM / 2) + (col >> 1)] = pack2(o[1][jd][0] * inv2, o[1][jd][1] * inv2);
        Oh[(row0 + 24) * (HDIM / 2) + (col >> 1)] = pack2(o[1][jd][2] * inv3, o[1][jd][3] * inv3);
    }
}

// ---------------------------------------------------------------------------
extern "C" void kernel_launch(void* const* d_in, const int* in_sizes, int n_in,
                              void* d_out, int out_size) {
    const float* x  = (const float*)d_in[0];
    const float* Wq = (const float*)d_in[1];
    const float* bq = (const float*)d_in[2];
    const float* Wk = (const float*)d_in[3];
    const float* bk = (const float*)d_in[4];
    const float* Wv = (const float*)d_in[5];
    const float* bv = (const float*)d_in[6];
    const float* Wo = (const float*)d_in[7];
    const float* bo = (const float*)d_in[8];
    float* out = (float*)d_out;

    uint32_t *xh, *wqh, *wkh, *wvh, *woh, *qh, *kh, *vh, *ah;
    cudaGetSymbolAddress((void**)&xh,  g_xh);
    cudaGetSymbolAddress((void**)&wqh, g_wqh);
    cudaGetSymbolAddress((void**)&wkh, g_wkh);
    cudaGetSymbolAddress((void**)&wvh, g_wvh);
    cudaGetSymbolAddress((void**)&woh, g_woh);
    cudaGetSymbolAddress((void**)&qh,  g_qh);
    cudaGetSymbolAddress((void**)&kh,  g_kh);
    cudaGetSymbolAddress((void**)&vh,  g_vh);
    cudaGetSymbolAddress((void**)&ah,  g_ah);

    const int total4 = XW4 + 4 * WW4;
    cvt_all_kernel<<<(total4 + 255) / 256, 256>>>(
        (const float4*)x, (const float4*)Wq, (const float4*)Wk,
        (const float4*)Wv, (const float4*)Wo,
        (uint2*)xh, (uint2*)wqh, (uint2*)wkh, (uint2*)wvh, (uint2*)woh);

    const int gemm_smem  = 3 * 32768;           // 96 KB
    const int flash_smem = 16384 + 2 * 32768;   // 80 KB
    cudaFuncSetAttribute(qkv_gemm_kernel,
                         cudaFuncAttributeMaxDynamicSharedMemorySize, gemm_smem);
    cudaFuncSetAttribute(gemm_f16_f32_kernel,
                         cudaFuncAttributeMaxDynamicSharedMemorySize, gemm_smem);
    cudaFuncSetAttribute(flash_f16_kernel,
                         cudaFuncAttributeMaxDynamicSharedMemorySize, flash_smem);

    qkv_gemm_kernel<<<dim3(HDIM / 128, TSEQ / 128, 3), 256, gemm_smem>>>(
        (const __half*)xh,
        (const __half*)wqh, (const __half*)wkh, (const __half*)wvh,
        bq, bk, bv, qh, kh, vh);

    flash_f16_kernel<<<dim3(TSEQ / 128, NHEADS), 128, flash_smem>>>(
        (const __half*)qh, (const __half*)kh, (const __half*)vh, ah);

    gemm_f16_f32_kernel<<<dim3(HDIM / 128, TSEQ / 128), 256, gemm_smem>>>(
        (const __half*)ah, (const __half*)woh, bo, out, TSEQ, HDIM, HDIM);
}